// round 1
// baseline (speedup 1.0000x reference)
#include <cuda_runtime.h>
#include <math.h>

#define TT   2048
#define BATCH 16
#define HD   512
#define G4   2048
#define NCTA 128
#define NTH  256
#define ROWS 16   // gate rows per CTA (4 hidden units x 4 gates)
#define HU   4    // hidden units per CTA

// Scratch (allocation-free rules: __device__ globals)
__device__ float g_x0[(size_t)TT * BATCH * G4];   // precomputed x@W_ih0^T + b0, [t*B+b][j]
__device__ float g_h0[2][BATCH * HD];             // layer0 h, double buffered
__device__ float g_h1[2][BATCH * HD];             // layer1 h, double buffered
__device__ unsigned int g_bar;                    // monotonic grid barrier counter

__global__ void init_kernel() {
    int i = blockIdx.x * blockDim.x + threadIdx.x;
    if (i == 0) g_bar = 0u;
    if (i < BATCH * HD) {
        g_h0[0][i] = 0.f; g_h0[1][i] = 0.f;
        g_h1[0][i] = 0.f; g_h1[1][i] = 0.f;
    }
}

// ---------------------------------------------------------------------------
// X0 GEMM: C[m][n] = bias[n] + sum_k A[m][k] * W[n][k]
// M=32768, N=2048, K=512.  64x64 tile, 256 threads, 4x4 per thread.
// ---------------------------------------------------------------------------
__global__ void __launch_bounds__(256) x0_gemm_kernel(
    const float* __restrict__ A, const float* __restrict__ W,
    const float* __restrict__ bias)
{
    __shared__ float As[16][68];
    __shared__ float Ws[16][68];
    int tid = threadIdx.x;
    int tx = tid & 15, ty = tid >> 4;
    int m0 = blockIdx.y * 64, n0 = blockIdx.x * 64;
    int lr = tid >> 2;
    int lc = (tid & 3) << 2;
    float acc[4][4] = {};
    for (int k0 = 0; k0 < 512; k0 += 16) {
        float4 av = *(const float4*)&A[(size_t)(m0 + lr) * 512 + k0 + lc];
        float4 wv = *(const float4*)&W[(size_t)(n0 + lr) * 512 + k0 + lc];
        As[lc + 0][lr] = av.x; As[lc + 1][lr] = av.y;
        As[lc + 2][lr] = av.z; As[lc + 3][lr] = av.w;
        Ws[lc + 0][lr] = wv.x; Ws[lc + 1][lr] = wv.y;
        Ws[lc + 2][lr] = wv.z; Ws[lc + 3][lr] = wv.w;
        __syncthreads();
        #pragma unroll
        for (int k = 0; k < 16; ++k) {
            float4 a4 = *(const float4*)&As[k][ty * 4];
            float4 w4 = *(const float4*)&Ws[k][tx * 4];
            float av_[4] = {a4.x, a4.y, a4.z, a4.w};
            float wv_[4] = {w4.x, w4.y, w4.z, w4.w};
            #pragma unroll
            for (int i = 0; i < 4; ++i)
                #pragma unroll
                for (int j = 0; j < 4; ++j)
                    acc[i][j] = fmaf(av_[i], wv_[j], acc[i][j]);
        }
        __syncthreads();
    }
    float4 bv = *(const float4*)&bias[n0 + tx * 4];
    #pragma unroll
    for (int i = 0; i < 4; ++i) {
        float4 r;
        r.x = acc[i][0] + bv.x; r.y = acc[i][1] + bv.y;
        r.z = acc[i][2] + bv.z; r.w = acc[i][3] + bv.w;
        *(float4*)&g_x0[(size_t)(m0 + ty * 4 + i) * (size_t)G4 + n0 + tx * 4] = r;
    }
}

// ---------------------------------------------------------------------------
// Persistent recurrent kernel. 128 CTAs, 1 per SM, weights resident in smem.
// One global barrier per timestep.
// ---------------------------------------------------------------------------
__global__ void __launch_bounds__(NTH, 1) slstm_kernel(
    const float* __restrict__ w_hh0,
    const float* __restrict__ w_ih1,
    const float* __restrict__ w_hh1,
    const float* __restrict__ b1,
    float* __restrict__ out)
{
    extern __shared__ float sm[];
    float* w0s  = sm;                       // 16*512 (xor-swizzled float4 cols)
    float* w1is = w0s  + ROWS * 512;
    float* w1hs = w1is + ROWS * 512;
    float* h0b  = w1hs + ROWS * 512;        // [16][516] padded
    float* h1b  = h0b  + BATCH * 516;       // [16][516]
    float* gb   = h1b  + BATCH * 516;       // [16][17] gate staging
    float* c0s  = gb   + BATCH * 17;        // 64 each
    float* n0s  = c0s + 64;
    float* c1s  = n0s + 64;
    float* n1s  = c1s + 64;
    float* hf0  = n1s + 64;
    float* hf1  = hf0 + 64;
    float* b1s  = hf1 + 64;                 // 16

    const int cta = blockIdx.x;
    const int tid = threadIdx.x;
    const int jj  = tid & 15;               // local gate-row
    const int bb  = tid >> 4;               // batch
    const int sw  = jj & 7;                 // xor swizzle key

    // Load the 3 recurrent weight slices into smem (swizzled), once.
    #pragma unroll
    for (int i = 0; i < 8; ++i) {
        int idx = tid + i * NTH;            // float4 index 0..2047
        int r = idx >> 7;                   // local row 0..15
        int c = idx & 127;                  // float4 col
        int grow = (r >> 2) * HD + cta * HU + (r & 3);
        int dst = r * 128 + (c ^ (r & 7));
        ((float4*)w0s)[dst]  = ((const float4*)(w_hh0 + (size_t)grow * 512))[c];
        ((float4*)w1is)[dst] = ((const float4*)(w_ih1 + (size_t)grow * 512))[c];
        ((float4*)w1hs)[dst] = ((const float4*)(w_hh1 + (size_t)grow * 512))[c];
    }
    if (tid < ROWS) {
        int grow = (tid >> 2) * HD + cta * HU + (tid & 3);
        b1s[tid] = b1[grow];
    }
    for (int i = tid; i < BATCH * 516; i += NTH) { h0b[i] = 0.f; h1b[i] = 0.f; }
    if (tid < 64) { c0s[tid] = 0.f; n0s[tid] = 0.f; c1s[tid] = 0.f; n1s[tid] = 0.f; }
    __syncthreads();

    const float4* h0v  = (const float4*)(h0b + bb * 516);
    const float4* h1v  = (const float4*)(h1b + bb * 516);
    const float4* w0v  = (const float4*)w0s  + jj * 128;
    const float4* w1iv = (const float4*)w1is + jj * 128;
    const float4* w1hv = (const float4*)w1hs + jj * 128;
    const int grow_j = (jj >> 2) * HD + cta * HU + (jj & 3);
    const int cb = tid >> 2, cu = tid & 3;          // cell mapping (tid<64)
    const int hidx = cb * HD + cta * HU + cu;       // into [B*H]

    for (int t = 0; t < TT; ++t) {
        // ---- layer 0: gates = X0[t] + h0_prev @ W_hh0^T ----
        float acc = g_x0[((size_t)t * BATCH + bb) * G4 + grow_j];
        #pragma unroll 16
        for (int k = 0; k < 128; ++k) {
            float4 h = h0v[k];
            float4 w = w0v[k ^ sw];
            acc = fmaf(h.x, w.x, acc); acc = fmaf(h.y, w.y, acc);
            acc = fmaf(h.z, w.z, acc); acc = fmaf(h.w, w.w, acc);
        }
        gb[bb * 17 + jj] = acc;
        __syncthreads();
        if (tid < 64) {
            float gi = gb[cb * 17 + 0  + cu];
            float gf = gb[cb * 17 + 4  + cu];
            float gg = gb[cb * 17 + 8  + cu];
            float go = gb[cb * 17 + 12 + cu];
            float iv = expf(gi);
            float fv = 1.f / (1.f + expf(-gf));
            float gv = tanhf(gg);
            float ov = 1.f / (1.f + expf(-go));
            float nv = fmaf(fv, n0s[tid], iv);
            float cv = fmaf(fv, c0s[tid], iv * gv);
            float hv = ov * (cv / (nv + 1e-8f));
            n0s[tid] = nv; c0s[tid] = cv; hf0[tid] = hv;
            g_h0[t & 1][hidx] = hv;
            __threadfence();
        }
        __syncthreads();

        // ---- grid barrier (monotonic counter) ----
        if (tid == 0) {
            atomicAdd(&g_bar, 1u);
            unsigned tgt = (unsigned)(t + 1) * (unsigned)NCTA;
            while (*((volatile unsigned int*)&g_bar) < tgt) { }
        }
        __syncthreads();

        // ---- reload full h0_cur and h1_prev (L2, bypass L1) ----
        const float* src0 = g_h0[t & 1];
        const float* src1 = g_h1[(t + 1) & 1];
        #pragma unroll
        for (int i = 0; i < 8; ++i) {
            int idx = tid + i * NTH;
            int r = idx >> 7, c = idx & 127;
            float4 v0 = __ldcg((const float4*)src0 + idx);
            float4 v1 = __ldcg((const float4*)src1 + idx);
            ((float4*)(h0b + r * 516))[c] = v0;
            ((float4*)(h1b + r * 516))[c] = v1;
        }
        __syncthreads();

        // ---- layer 1: gates = h0_cur @ W_ih1^T + h1_prev @ W_hh1^T + b1 ----
        float acc1 = b1s[jj];
        #pragma unroll 8
        for (int k = 0; k < 128; ++k) {
            float4 x  = h0v[k];
            float4 wi = w1iv[k ^ sw];
            float4 h  = h1v[k];
            float4 wh = w1hv[k ^ sw];
            acc1 = fmaf(x.x, wi.x, acc1); acc1 = fmaf(x.y, wi.y, acc1);
            acc1 = fmaf(x.z, wi.z, acc1); acc1 = fmaf(x.w, wi.w, acc1);
            acc1 = fmaf(h.x, wh.x, acc1); acc1 = fmaf(h.y, wh.y, acc1);
            acc1 = fmaf(h.z, wh.z, acc1); acc1 = fmaf(h.w, wh.w, acc1);
        }
        gb[bb * 17 + jj] = acc1;
        __syncthreads();
        if (tid < 64) {
            float gi = gb[cb * 17 + 0  + cu];
            float gf = gb[cb * 17 + 4  + cu];
            float gg = gb[cb * 17 + 8  + cu];
            float go = gb[cb * 17 + 12 + cu];
            float iv = expf(gi);
            float fv = 1.f / (1.f + expf(-gf));
            float gv = tanhf(gg);
            float ov = 1.f / (1.f + expf(-go));
            float nv = fmaf(fv, n1s[tid], iv);
            float cv = fmaf(fv, c1s[tid], iv * gv);
            float hv = ov * (cv / (nv + 1e-8f));
            n1s[tid] = nv; c1s[tid] = cv; hf1[tid] = hv;
            g_h1[t & 1][hidx] = hv;
            out[(size_t)t * (BATCH * HD) + hidx] = hv;   // output_seq
            __threadfence();
        }
        __syncthreads();
    }

    // Final states: hn[2,B,H], cn[2,B,H], nn[2,B,H] after output_seq
    if (tid < 64) {
        size_t base = (size_t)TT * BATCH * HD;
        out[base + 0 * (BATCH * HD) + hidx] = hf0[tid];
        out[base + 1 * (BATCH * HD) + hidx] = hf1[tid];
        out[base + 2 * (BATCH * HD) + hidx] = c0s[tid];
        out[base + 3 * (BATCH * HD) + hidx] = c1s[tid];
        out[base + 4 * (BATCH * HD) + hidx] = n0s[tid];
        out[base + 5 * (BATCH * HD) + hidx] = n1s[tid];
    }
}

extern "C" void kernel_launch(void* const* d_in, const int* in_sizes, int n_in,
                              void* d_out, int out_size) {
    (void)in_sizes; (void)n_in; (void)out_size;
    const float* input  = (const float*)d_in[0];
    const float* w_ih0  = (const float*)d_in[1];
    const float* w_hh0  = (const float*)d_in[2];
    const float* b0     = (const float*)d_in[3];
    const float* w_ih1  = (const float*)d_in[4];
    const float* w_hh1  = (const float*)d_in[5];
    const float* b1     = (const float*)d_in[6];
    float* out = (float*)d_out;

    int smem_bytes = (3 * ROWS * 512 + 2 * BATCH * 516 + BATCH * 17 + 6 * 64 + 16) * 4;
    cudaFuncSetAttribute(slstm_kernel, cudaFuncAttributeMaxDynamicSharedMemorySize, smem_bytes);

    init_kernel<<<32, 256>>>();
    x0_gemm_kernel<<<dim3(G4 / 64, (TT * BATCH) / 64), 256>>>(input, w_ih0, b0);
    slstm_kernel<<<NCTA, NTH, smem_bytes>>>(w_hh0, w_ih1, w_hh1, b1, out);
}

// round 2
// speedup vs baseline: 1.6257x; 1.6257x over previous
#include <cuda_runtime.h>
#include <math.h>

#define TT    2048
#define BATCH 16
#define HD    512
#define G4    2048
#define NCTA  128
#define NTH   256
#define ROWS  16   // gate rows per CTA per layer (4 gates x 4 units)
#define HU    4    // hidden units per CTA

// Scratch (__device__ globals per allocation-free rules)
__device__ float g_x0[(size_t)TT * NCTA * 256];   // [t][cta][b][16 local rows]
__device__ float g_h0[2][BATCH * HD];
__device__ float g_h1[2][BATCH * HD];
__device__ unsigned int g_bar;

__global__ void init_kernel() {
    int i = blockIdx.x * blockDim.x + threadIdx.x;
    if (i == 0) g_bar = 0u;
    if (i < BATCH * HD) {
        g_h0[0][i] = 0.f; g_h0[1][i] = 0.f;
        g_h1[0][i] = 0.f; g_h1[1][i] = 0.f;
    }
}

// ---------------------------------------------------------------------------
// X0 GEMM: out[t][cta][b][row] = b0[n] + sum_k input[m][k]*W[n][k]
// m = t*16+b (M=32768), n = g*512 + cta*4 + u (N=2048), row = g*4+u, K=512
// ---------------------------------------------------------------------------
__global__ void __launch_bounds__(256) x0_gemm_kernel(
    const float* __restrict__ A, const float* __restrict__ W,
    const float* __restrict__ bias)
{
    __shared__ float As[16][68];
    __shared__ float Ws[16][68];
    int tid = threadIdx.x;
    int tx = tid & 15, ty = tid >> 4;
    int m0 = blockIdx.y * 64, n0 = blockIdx.x * 64;
    int lr = tid >> 2;
    int lc = (tid & 3) << 2;
    float acc[4][4] = {};
    for (int k0 = 0; k0 < 512; k0 += 16) {
        float4 av = *(const float4*)&A[(size_t)(m0 + lr) * 512 + k0 + lc];
        float4 wv = *(const float4*)&W[(size_t)(n0 + lr) * 512 + k0 + lc];
        As[lc + 0][lr] = av.x; As[lc + 1][lr] = av.y;
        As[lc + 2][lr] = av.z; As[lc + 3][lr] = av.w;
        Ws[lc + 0][lr] = wv.x; Ws[lc + 1][lr] = wv.y;
        Ws[lc + 2][lr] = wv.z; Ws[lc + 3][lr] = wv.w;
        __syncthreads();
        #pragma unroll
        for (int k = 0; k < 16; ++k) {
            float4 a4 = *(const float4*)&As[k][ty * 4];
            float4 w4 = *(const float4*)&Ws[k][tx * 4];
            float av_[4] = {a4.x, a4.y, a4.z, a4.w};
            float wv_[4] = {w4.x, w4.y, w4.z, w4.w};
            #pragma unroll
            for (int i = 0; i < 4; ++i)
                #pragma unroll
                for (int j = 0; j < 4; ++j)
                    acc[i][j] = fmaf(av_[i], wv_[j], acc[i][j]);
        }
        __syncthreads();
    }
    float4 bv = *(const float4*)&bias[n0 + tx * 4];
    int n = n0 + tx * 4;
    int g = n >> 9;              // gate 0..3
    int cta = (n >> 2) & 127;    // owning CTA
    #pragma unroll
    for (int i = 0; i < 4; ++i) {
        int m = m0 + ty * 4 + i;
        int t = m >> 4, b = m & 15;
        float4 r;
        r.x = acc[i][0] + bv.x; r.y = acc[i][1] + bv.y;
        r.z = acc[i][2] + bv.z; r.w = acc[i][3] + bv.w;
        size_t dst = (((size_t)t * NCTA + cta) * 16 + b) * 16 + g * 4;
        *(float4*)&g_x0[dst] = r;
    }
}

// ---------------------------------------------------------------------------
// Persistent recurrent kernel. 128 CTAs, register-tiled GEMMs with K split
// across warps. Weights resident in smem for the whole loop.
// ---------------------------------------------------------------------------
__global__ void __launch_bounds__(NTH, 1) slstm_kernel(
    const float* __restrict__ w_hh0,
    const float* __restrict__ w_ih1,
    const float* __restrict__ w_hh1,
    const float* __restrict__ b1,
    float* __restrict__ out)
{
    extern __shared__ float sm[];
    float* w0s  = sm;                        // 2048 f4 (perm layout)
    float* w1is = w0s  + ROWS * 512;
    float* w1hs = w1is + ROWS * 512;
    float* h0b  = w1hs + ROWS * 512;         // 16 x 129 f4 (stride 516 floats)
    float* h1b  = h0b  + BATCH * 516;
    float* pb   = h1b  + BATCH * 516;        // 8 warps x 264
    float* gb   = pb   + 8 * 264;            // 16 x 17
    float* c0s  = gb   + BATCH * 17;
    float* n0s  = c0s + 64;
    float* c1s  = n0s + 64;
    float* n1s  = c1s + 64;
    float* hf0  = n1s + 64;
    float* hf1  = hf0 + 64;
    float* b1s  = hf1 + 64;                  // 16

    const int cta  = blockIdx.x;
    const int tid  = threadIdx.x;
    const int w    = tid >> 5;               // warp = k-chunk owner
    const int lane = tid & 31;
    const int r2   = lane >> 2;              // rows {2r2, 2r2+1}
    const int bq   = lane & 3;               // batches {bq, bq+4, bq+8, bq+12}

    float4* w0f  = (float4*)w0s;
    float4* w1if = (float4*)w1is;
    float4* w1hf = (float4*)w1hs;
    float4* h0f  = (float4*)h0b;
    float4* h1f  = (float4*)h1b;

    // Load weight slices into smem with permuted layout:
    //   f4 (row, c) -> index c*16 + (row&1)*8 + (row>>1)
    #pragma unroll
    for (int i = 0; i < 8; ++i) {
        int idx = tid + i * NTH;             // 0..2047
        int r = idx >> 7;
        int c = idx & 127;
        int grow = (r >> 2) * HD + cta * HU + (r & 3);
        int dst = c * 16 + (r & 1) * 8 + (r >> 1);
        w0f[dst]  = ((const float4*)(w_hh0 + (size_t)grow * 512))[c];
        w1if[dst] = ((const float4*)(w_ih1 + (size_t)grow * 512))[c];
        w1hf[dst] = ((const float4*)(w_hh1 + (size_t)grow * 512))[c];
    }
    if (tid < ROWS) {
        int grow = (tid >> 2) * HD + cta * HU + (tid & 3);
        b1s[tid] = b1[grow];
    }
    for (int i = tid; i < BATCH * 516; i += NTH) { h0b[i] = 0.f; h1b[i] = 0.f; }
    if (tid < 64) { c0s[tid] = 0.f; n0s[tid] = 0.f; c1s[tid] = 0.f; n1s[tid] = 0.f; }
    __syncthreads();

    const int kb = w * 16;                   // f4 k-range start for this warp
    const int cb = tid >> 2, cu = tid & 3;   // cell mapping (tid<64)
    const int hidx = cb * HD + cta * HU + cu;
    const int rb = tid >> 4, rr = tid & 15;  // reduction mapping (b, row)
    const float bias1 = b1s[rr];

    for (int t = 0; t < TT; ++t) {
        // Coalesced x0 prefetch: one float per thread
        float x0v = __ldcg(&g_x0[(((size_t)t * NCTA + cta) * 256) + tid]);

        // ---- layer 0 GEMM: partials over k in [kb, kb+16) f4 ----
        float a0[4] = {0.f, 0.f, 0.f, 0.f};
        float a1[4] = {0.f, 0.f, 0.f, 0.f};
        #pragma unroll
        for (int kv = 0; kv < 16; ++kv) {
            int k4 = kb + kv;
            float4 wa = w0f[k4 * 16 + r2];
            float4 wb = w0f[k4 * 16 + 8 + r2];
            #pragma unroll
            for (int m = 0; m < 4; ++m) {
                float4 h = h0f[(bq + 4 * m) * 129 + k4];
                a0[m] = fmaf(wa.x, h.x, a0[m]); a0[m] = fmaf(wa.y, h.y, a0[m]);
                a0[m] = fmaf(wa.z, h.z, a0[m]); a0[m] = fmaf(wa.w, h.w, a0[m]);
                a1[m] = fmaf(wb.x, h.x, a1[m]); a1[m] = fmaf(wb.y, h.y, a1[m]);
                a1[m] = fmaf(wb.z, h.z, a1[m]); a1[m] = fmaf(wb.w, h.w, a1[m]);
            }
        }
        #pragma unroll
        for (int m = 0; m < 4; ++m) {
            pb[w * 264 + (bq + 4 * m) * 16 + 2 * r2]     = a0[m];
            pb[w * 264 + (bq + 4 * m) * 16 + 2 * r2 + 1] = a1[m];
        }
        __syncthreads();

        // ---- reduce 8 warp-partials + x0 ----
        {
            float g = x0v;
            #pragma unroll
            for (int ww = 0; ww < 8; ++ww) g += pb[ww * 264 + tid];
            gb[rb * 17 + rr] = g;
        }
        __syncthreads();

        // ---- layer 0 cell update ----
        if (tid < 64) {
            float gi = gb[cb * 17 + 0  + cu];
            float gf = gb[cb * 17 + 4  + cu];
            float gg = gb[cb * 17 + 8  + cu];
            float go = gb[cb * 17 + 12 + cu];
            float iv = expf(gi);
            float fv = 1.f / (1.f + expf(-gf));
            float gv = tanhf(gg);
            float ov = 1.f / (1.f + expf(-go));
            float nv = fmaf(fv, n0s[tid], iv);
            float cv = fmaf(fv, c0s[tid], iv * gv);
            float hv = ov * (cv / (nv + 1e-8f));
            n0s[tid] = nv; c0s[tid] = cv; hf0[tid] = hv;
            g_h0[t & 1][hidx] = hv;
            __threadfence();
        }
        __syncthreads();

        // ---- grid barrier (monotonic counter) ----
        if (tid == 0) {
            atomicAdd(&g_bar, 1u);
            unsigned tgt = (unsigned)(t + 1) * (unsigned)NCTA;
            while (*((volatile unsigned int*)&g_bar) < tgt) { }
        }
        __syncthreads();

        // ---- reload h0(t) and h1(t-1) into smem ----
        {
            const float4* s0 = (const float4*)g_h0[t & 1];
            const float4* s1 = (const float4*)g_h1[(t + 1) & 1];
            #pragma unroll
            for (int i = 0; i < 8; ++i) {
                int idx = tid + i * NTH;     // 0..2047 f4
                int b = idx >> 7, c = idx & 127;
                h0f[b * 129 + c] = __ldcg(s0 + idx);
                h1f[b * 129 + c] = __ldcg(s1 + idx);
            }
        }
        __syncthreads();

        // ---- layer 1 GEMM: wi@h0cur + wh@h1prev ----
        #pragma unroll
        for (int m = 0; m < 4; ++m) { a0[m] = 0.f; a1[m] = 0.f; }
        #pragma unroll
        for (int kv = 0; kv < 16; ++kv) {
            int k4 = kb + kv;
            float4 wia = w1if[k4 * 16 + r2];
            float4 wib = w1if[k4 * 16 + 8 + r2];
            float4 wha = w1hf[k4 * 16 + r2];
            float4 whb = w1hf[k4 * 16 + 8 + r2];
            #pragma unroll
            for (int m = 0; m < 4; ++m) {
                float4 x = h0f[(bq + 4 * m) * 129 + k4];
                float4 h = h1f[(bq + 4 * m) * 129 + k4];
                a0[m] = fmaf(wia.x, x.x, a0[m]); a0[m] = fmaf(wia.y, x.y, a0[m]);
                a0[m] = fmaf(wia.z, x.z, a0[m]); a0[m] = fmaf(wia.w, x.w, a0[m]);
                a0[m] = fmaf(wha.x, h.x, a0[m]); a0[m] = fmaf(wha.y, h.y, a0[m]);
                a0[m] = fmaf(wha.z, h.z, a0[m]); a0[m] = fmaf(wha.w, h.w, a0[m]);
                a1[m] = fmaf(wib.x, x.x, a1[m]); a1[m] = fmaf(wib.y, x.y, a1[m]);
                a1[m] = fmaf(wib.z, x.z, a1[m]); a1[m] = fmaf(wib.w, x.w, a1[m]);
                a1[m] = fmaf(whb.x, h.x, a1[m]); a1[m] = fmaf(whb.y, h.y, a1[m]);
                a1[m] = fmaf(whb.z, h.z, a1[m]); a1[m] = fmaf(whb.w, h.w, a1[m]);
            }
        }
        #pragma unroll
        for (int m = 0; m < 4; ++m) {
            pb[w * 264 + (bq + 4 * m) * 16 + 2 * r2]     = a0[m];
            pb[w * 264 + (bq + 4 * m) * 16 + 2 * r2 + 1] = a1[m];
        }
        __syncthreads();

        // ---- reduce + bias ----
        {
            float g = bias1;
            #pragma unroll
            for (int ww = 0; ww < 8; ++ww) g += pb[ww * 264 + tid];
            gb[rb * 17 + rr] = g;
        }
        __syncthreads();

        // ---- layer 1 cell update + output ----
        if (tid < 64) {
            float gi = gb[cb * 17 + 0  + cu];
            float gf = gb[cb * 17 + 4  + cu];
            float gg = gb[cb * 17 + 8  + cu];
            float go = gb[cb * 17 + 12 + cu];
            float iv = expf(gi);
            float fv = 1.f / (1.f + expf(-gf));
            float gv = tanhf(gg);
            float ov = 1.f / (1.f + expf(-go));
            float nv = fmaf(fv, n1s[tid], iv);
            float cv = fmaf(fv, c1s[tid], iv * gv);
            float hv = ov * (cv / (nv + 1e-8f));
            n1s[tid] = nv; c1s[tid] = cv; hf1[tid] = hv;
            g_h1[t & 1][hidx] = hv;
            out[(size_t)t * (BATCH * HD) + hidx] = hv;
            __threadfence();
        }
        __syncthreads();
    }

    // Final states after output_seq: hn[2,B,H], cn[2,B,H], nn[2,B,H]
    if (tid < 64) {
        size_t base = (size_t)TT * BATCH * HD;
        out[base + 0 * (BATCH * HD) + hidx] = hf0[tid];
        out[base + 1 * (BATCH * HD) + hidx] = hf1[tid];
        out[base + 2 * (BATCH * HD) + hidx] = c0s[tid];
        out[base + 3 * (BATCH * HD) + hidx] = c1s[tid];
        out[base + 4 * (BATCH * HD) + hidx] = n0s[tid];
        out[base + 5 * (BATCH * HD) + hidx] = n1s[tid];
    }
}

extern "C" void kernel_launch(void* const* d_in, const int* in_sizes, int n_in,
                              void* d_out, int out_size) {
    (void)in_sizes; (void)n_in; (void)out_size;
    const float* input  = (const float*)d_in[0];
    const float* w_ih0  = (const float*)d_in[1];
    const float* w_hh0  = (const float*)d_in[2];
    const float* b0     = (const float*)d_in[3];
    const float* w_ih1  = (const float*)d_in[4];
    const float* w_hh1  = (const float*)d_in[5];
    const float* b1     = (const float*)d_in[6];
    float* out = (float*)d_out;

    int smem_bytes = (3 * ROWS * 512 + 2 * BATCH * 516 + 8 * 264 + BATCH * 17
                      + 6 * 64 + 16) * 4;
    cudaFuncSetAttribute(slstm_kernel, cudaFuncAttributeMaxDynamicSharedMemorySize, smem_bytes);

    init_kernel<<<32, 256>>>();
    x0_gemm_kernel<<<dim3(G4 / 64, (TT * BATCH) / 64), 256>>>(input, w_ih0, b0);
    slstm_kernel<<<NCTA, NTH, smem_bytes>>>(w_hh0, w_ih1, w_hh1, b1, out);
}

// round 3
// speedup vs baseline: 1.6397x; 1.0086x over previous
#include <cuda_runtime.h>
#include <math.h>

#define TT    2048
#define BATCH 16
#define HD    512
#define G4    2048
#define NCTA  128
#define NTH   256
#define ROWS  16   // gate rows per CTA per layer (4 gates x 4 units)
#define HU    4    // hidden units per CTA
#define BH    (BATCH * HD)

// Scratch (__device__ globals per allocation-free rules)
__device__ float g_x0[(size_t)TT * NCTA * 256];   // [t][cta][b][16 local rows]
__device__ float g_h0[2][BH];
__device__ float g_h1[2][BH];
__device__ unsigned g_ctr[64];                    // [0]=A (h0 steps), [32]=B (h1 steps)

__device__ __forceinline__ void cta_arrive(unsigned* p) {
    asm volatile("red.release.gpu.add.u32 [%0], %1;" :: "l"(p), "r"(1u) : "memory");
}
__device__ __forceinline__ void cta_spin(unsigned* p, unsigned tgt) {
    unsigned v;
    do {
        asm volatile("ld.acquire.gpu.u32 %0, [%1];" : "=r"(v) : "l"(p) : "memory");
    } while (v < tgt);
}

__global__ void init_kernel() {
    int i = blockIdx.x * blockDim.x + threadIdx.x;
    if (i < 64) g_ctr[i] = 0u;
}

// ---------------------------------------------------------------------------
// X0 GEMM: out[t][cta][b][row] = b0[n] + sum_k input[m][k]*W[n][k]
// ---------------------------------------------------------------------------
__global__ void __launch_bounds__(256) x0_gemm_kernel(
    const float* __restrict__ A, const float* __restrict__ W,
    const float* __restrict__ bias)
{
    __shared__ float As[16][68];
    __shared__ float Ws[16][68];
    int tid = threadIdx.x;
    int tx = tid & 15, ty = tid >> 4;
    int m0 = blockIdx.y * 64, n0 = blockIdx.x * 64;
    int lr = tid >> 2;
    int lc = (tid & 3) << 2;
    float acc[4][4] = {};
    for (int k0 = 0; k0 < 512; k0 += 16) {
        float4 av = *(const float4*)&A[(size_t)(m0 + lr) * 512 + k0 + lc];
        float4 wv = *(const float4*)&W[(size_t)(n0 + lr) * 512 + k0 + lc];
        As[lc + 0][lr] = av.x; As[lc + 1][lr] = av.y;
        As[lc + 2][lr] = av.z; As[lc + 3][lr] = av.w;
        Ws[lc + 0][lr] = wv.x; Ws[lc + 1][lr] = wv.y;
        Ws[lc + 2][lr] = wv.z; Ws[lc + 3][lr] = wv.w;
        __syncthreads();
        #pragma unroll
        for (int k = 0; k < 16; ++k) {
            float4 a4 = *(const float4*)&As[k][ty * 4];
            float4 w4 = *(const float4*)&Ws[k][tx * 4];
            float av_[4] = {a4.x, a4.y, a4.z, a4.w};
            float wv_[4] = {w4.x, w4.y, w4.z, w4.w};
            #pragma unroll
            for (int i = 0; i < 4; ++i)
                #pragma unroll
                for (int j = 0; j < 4; ++j)
                    acc[i][j] = fmaf(av_[i], wv_[j], acc[i][j]);
        }
        __syncthreads();
    }
    float4 bv = *(const float4*)&bias[n0 + tx * 4];
    int n = n0 + tx * 4;
    int g = n >> 9;
    int cta = (n >> 2) & 127;
    #pragma unroll
    for (int i = 0; i < 4; ++i) {
        int m = m0 + ty * 4 + i;
        int t = m >> 4, b = m & 15;
        float4 r;
        r.x = acc[i][0] + bv.x; r.y = acc[i][1] + bv.y;
        r.z = acc[i][2] + bv.z; r.w = acc[i][3] + bv.w;
        size_t dst = (((size_t)t * NCTA + cta) * 16 + b) * 16 + g * 4;
        *(float4*)&g_x0[dst] = r;
    }
}

// ---------------------------------------------------------------------------
// Persistent recurrent kernel, layer-pipelined: slot t = {L0 step t, L1 step t-1}
// ---------------------------------------------------------------------------
__global__ void __launch_bounds__(NTH, 1) slstm_kernel(
    const float* __restrict__ w_hh0,
    const float* __restrict__ w_ih1,
    const float* __restrict__ w_hh1,
    const float* __restrict__ b1,
    float* __restrict__ out)
{
    extern __shared__ float sm[];
    float* w0s  = sm;                        // 2048 f4 (perm layout)
    float* w1is = w0s  + ROWS * 512;
    float* w1hs = w1is + ROWS * 512;
    float* h0b  = w1hs + ROWS * 512;         // 16 x 129 f4
    float* h1b  = h0b  + BATCH * 516;
    float* pb   = h1b  + BATCH * 516;        // 8 warps x 264
    float* gb   = pb   + 8 * 264;            // 16 x 17
    float* c0s  = gb   + BATCH * 17;
    float* n0s  = c0s + 64;
    float* c1s  = n0s + 64;
    float* n1s  = c1s + 64;
    float* hf0  = n1s + 64;
    float* hf1  = hf0 + 64;
    float* b1s  = hf1 + 64;                  // 16

    const int cta  = blockIdx.x;
    const int tid  = threadIdx.x;
    const int w    = tid >> 5;
    const int lane = tid & 31;
    const int r2   = lane >> 2;
    const int bq   = lane & 3;

    float4* w0f  = (float4*)w0s;
    float4* w1if = (float4*)w1is;
    float4* w1hf = (float4*)w1hs;
    float4* h0f  = (float4*)h0b;
    float4* h1f  = (float4*)h1b;

    // Load weight slices into smem, permuted: f4 (row,c) -> c*16 + (row&1)*8 + (row>>1)
    #pragma unroll
    for (int i = 0; i < 8; ++i) {
        int idx = tid + i * NTH;
        int r = idx >> 7;
        int c = idx & 127;
        int grow = (r >> 2) * HD + cta * HU + (r & 3);
        int dst = c * 16 + (r & 1) * 8 + (r >> 1);
        w0f[dst]  = ((const float4*)(w_hh0 + (size_t)grow * 512))[c];
        w1if[dst] = ((const float4*)(w_ih1 + (size_t)grow * 512))[c];
        w1hf[dst] = ((const float4*)(w_hh1 + (size_t)grow * 512))[c];
    }
    if (tid < ROWS) {
        int grow = (tid >> 2) * HD + cta * HU + (tid & 3);
        b1s[tid] = b1[grow];
    }
    for (int i = tid; i < BATCH * 516; i += NTH) { h0b[i] = 0.f; h1b[i] = 0.f; }
    if (tid < 64) { c0s[tid] = 0.f; n0s[tid] = 0.f; c1s[tid] = 0.f; n1s[tid] = 0.f; }
    __syncthreads();

    const int kb = w * 16;
    const int cb = tid >> 2, cu = tid & 3;   // cell mapping (tid<64)
    const int hidx = cb * HD + cta * HU + cu;
    const float bias1 = b1s[tid & 15];
    unsigned* ctrA = &g_ctr[0];
    unsigned* ctrB = &g_ctr[32];

    for (int t = 0; t < TT; ++t) {
        float x0v = __ldcg(&g_x0[(((size_t)t * NCTA + cta) * 256) + tid]);

        // ---- L0 GEMM (h0f = h0(t-1)) ----
        float a0[4] = {0.f, 0.f, 0.f, 0.f};
        float a1[4] = {0.f, 0.f, 0.f, 0.f};
        #pragma unroll
        for (int kv = 0; kv < 16; ++kv) {
            int k4 = kb + kv;
            float4 wa = w0f[k4 * 16 + r2];
            float4 wb = w0f[k4 * 16 + 8 + r2];
            #pragma unroll
            for (int m = 0; m < 4; ++m) {
                float4 h = h0f[(bq + 4 * m) * 129 + k4];
                a0[m] = fmaf(wa.x, h.x, a0[m]); a0[m] = fmaf(wa.y, h.y, a0[m]);
                a0[m] = fmaf(wa.z, h.z, a0[m]); a0[m] = fmaf(wa.w, h.w, a0[m]);
                a1[m] = fmaf(wb.x, h.x, a1[m]); a1[m] = fmaf(wb.y, h.y, a1[m]);
                a1[m] = fmaf(wb.z, h.z, a1[m]); a1[m] = fmaf(wb.w, h.w, a1[m]);
            }
        }
        #pragma unroll
        for (int m = 0; m < 4; ++m) {
            pb[w * 264 + (bq + 4 * m) * 16 + 2 * r2]     = a0[m];
            pb[w * 264 + (bq + 4 * m) * 16 + 2 * r2 + 1] = a1[m];
        }
        __syncthreads();

        // ---- reduce0 (+x0) ; overlapped spin on B (h1(t-2) published) ----
        {
            float g = x0v;
            #pragma unroll
            for (int ww = 0; ww < 8; ++ww) g += pb[ww * 264 + tid];
            gb[(tid >> 4) * 17 + (tid & 15)] = g;
        }
        if (t >= 2 && tid == 255) cta_spin(ctrB, 128u * (unsigned)(t - 1));
        __syncthreads();

        // ---- cell0 + arrive A (warps 0-1) overlapped with h1 reload ----
        if (tid < 64) {
            float gi = gb[cb * 17 + 0  + cu];
            float gf = gb[cb * 17 + 4  + cu];
            float gg = gb[cb * 17 + 8  + cu];
            float go = gb[cb * 17 + 12 + cu];
            float iv = expf(gi);
            float fv = 1.f / (1.f + expf(-gf));
            float gv = tanhf(gg);
            float ov = 1.f / (1.f + expf(-go));
            float nv = fmaf(fv, n0s[tid], iv);
            float cv = fmaf(fv, c0s[tid], iv * gv);
            float hv = ov * (cv / (nv + 1e-8f));
            n0s[tid] = nv; c0s[tid] = cv; hf0[tid] = hv;
            g_h0[t & 1][hidx] = hv;
            asm volatile("bar.sync 1, 64;" ::: "memory");
            if (tid == 0) cta_arrive(ctrA);
        }
        if (t >= 2) {  // h1(t-2) lives in g_h1[t&1]
            const float4* s1 = (const float4*)g_h1[t & 1];
            #pragma unroll
            for (int i = 0; i < 8; ++i) {
                int idx = tid + i * NTH;
                int b = idx >> 7, c = idx & 127;
                h1f[b * 129 + c] = __ldcg(s1 + idx);
            }
        }
        __syncthreads();

        // ---- L1 GEMM for step t-1 (h0f = h0(t-1), h1f = h1(t-2)) ----
        if (t > 0) {
            #pragma unroll
            for (int m = 0; m < 4; ++m) { a0[m] = 0.f; a1[m] = 0.f; }
            #pragma unroll
            for (int kv = 0; kv < 16; ++kv) {
                int k4 = kb + kv;
                float4 wia = w1if[k4 * 16 + r2];
                float4 wib = w1if[k4 * 16 + 8 + r2];
                float4 wha = w1hf[k4 * 16 + r2];
                float4 whb = w1hf[k4 * 16 + 8 + r2];
                #pragma unroll
                for (int m = 0; m < 4; ++m) {
                    float4 x = h0f[(bq + 4 * m) * 129 + k4];
                    float4 h = h1f[(bq + 4 * m) * 129 + k4];
                    a0[m] = fmaf(wia.x, x.x, a0[m]); a0[m] = fmaf(wia.y, x.y, a0[m]);
                    a0[m] = fmaf(wia.z, x.z, a0[m]); a0[m] = fmaf(wia.w, x.w, a0[m]);
                    a0[m] = fmaf(wha.x, h.x, a0[m]); a0[m] = fmaf(wha.y, h.y, a0[m]);
                    a0[m] = fmaf(wha.z, h.z, a0[m]); a0[m] = fmaf(wha.w, h.w, a0[m]);
                    a1[m] = fmaf(wib.x, x.x, a1[m]); a1[m] = fmaf(wib.y, x.y, a1[m]);
                    a1[m] = fmaf(wib.z, x.z, a1[m]); a1[m] = fmaf(wib.w, x.w, a1[m]);
                    a1[m] = fmaf(whb.x, h.x, a1[m]); a1[m] = fmaf(whb.y, h.y, a1[m]);
                    a1[m] = fmaf(whb.z, h.z, a1[m]); a1[m] = fmaf(whb.w, h.w, a1[m]);
                }
            }
            #pragma unroll
            for (int m = 0; m < 4; ++m) {
                pb[w * 264 + (bq + 4 * m) * 16 + 2 * r2]     = a0[m];
                pb[w * 264 + (bq + 4 * m) * 16 + 2 * r2 + 1] = a1[m];
            }
            __syncthreads();
            {
                float g = bias1;
                #pragma unroll
                for (int ww = 0; ww < 8; ++ww) g += pb[ww * 264 + tid];
                gb[(tid >> 4) * 17 + (tid & 15)] = g;
            }
        }
        // spin on A (h0(t) published by all) — others arrived one gemm1 ago
        if (tid == 255) cta_spin(ctrA, 128u * (unsigned)(t + 1));
        __syncthreads();

        // ---- cell1 (h1(t-1)) + arrive B, overlapped with h0 reload ----
        if (t > 0 && tid < 64) {
            float gi = gb[cb * 17 + 0  + cu];
            float gf = gb[cb * 17 + 4  + cu];
            float gg = gb[cb * 17 + 8  + cu];
            float go = gb[cb * 17 + 12 + cu];
            float iv = expf(gi);
            float fv = 1.f / (1.f + expf(-gf));
            float gv = tanhf(gg);
            float ov = 1.f / (1.f + expf(-go));
            float nv = fmaf(fv, n1s[tid], iv);
            float cv = fmaf(fv, c1s[tid], iv * gv);
            float hv = ov * (cv / (nv + 1e-8f));
            n1s[tid] = nv; c1s[tid] = cv; hf1[tid] = hv;
            g_h1[(t - 1) & 1][hidx] = hv;
            out[(size_t)(t - 1) * BH + hidx] = hv;
            asm volatile("bar.sync 1, 64;" ::: "memory");
            if (tid == 0) cta_arrive(ctrB);
        }
        {   // reload h0(t)
            const float4* s0 = (const float4*)g_h0[t & 1];
            #pragma unroll
            for (int i = 0; i < 8; ++i) {
                int idx = tid + i * NTH;
                int b = idx >> 7, c = idx & 127;
                h0f[b * 129 + c] = __ldcg(s0 + idx);
            }
        }
        __syncthreads();
    }

    // ---- epilogue: L1 step TT-1 (h0f = h0(TT-1), need h1(TT-2)) ----
    if (tid == 255) cta_spin(ctrB, 128u * (unsigned)(TT - 1));
    __syncthreads();
    {
        const float4* s1 = (const float4*)g_h1[TT & 1];   // h1(TT-2)
        #pragma unroll
        for (int i = 0; i < 8; ++i) {
            int idx = tid + i * NTH;
            int b = idx >> 7, c = idx & 127;
            h1f[b * 129 + c] = __ldcg(s1 + idx);
        }
    }
    __syncthreads();
    {
        float a0[4] = {0.f, 0.f, 0.f, 0.f};
        float a1[4] = {0.f, 0.f, 0.f, 0.f};
        #pragma unroll
        for (int kv = 0; kv < 16; ++kv) {
            int k4 = kb + kv;
            float4 wia = w1if[k4 * 16 + r2];
            float4 wib = w1if[k4 * 16 + 8 + r2];
            float4 wha = w1hf[k4 * 16 + r2];
            float4 whb = w1hf[k4 * 16 + 8 + r2];
            #pragma unroll
            for (int m = 0; m < 4; ++m) {
                float4 x = h0f[(bq + 4 * m) * 129 + k4];
                float4 h = h1f[(bq + 4 * m) * 129 + k4];
                a0[m] = fmaf(wia.x, x.x, a0[m]); a0[m] = fmaf(wia.y, x.y, a0[m]);
                a0[m] = fmaf(wia.z, x.z, a0[m]); a0[m] = fmaf(wia.w, x.w, a0[m]);
                a0[m] = fmaf(wha.x, h.x, a0[m]); a0[m] = fmaf(wha.y, h.y, a0[m]);
                a0[m] = fmaf(wha.z, h.z, a0[m]); a0[m] = fmaf(wha.w, h.w, a0[m]);
                a1[m] = fmaf(wib.x, x.x, a1[m]); a1[m] = fmaf(wib.y, x.y, a1[m]);
                a1[m] = fmaf(wib.z, x.z, a1[m]); a1[m] = fmaf(wib.w, x.w, a1[m]);
                a1[m] = fmaf(whb.x, h.x, a1[m]); a1[m] = fmaf(whb.y, h.y, a1[m]);
                a1[m] = fmaf(whb.z, h.z, a1[m]); a1[m] = fmaf(whb.w, h.w, a1[m]);
            }
        }
        #pragma unroll
        for (int m = 0; m < 4; ++m) {
            pb[w * 264 + (bq + 4 * m) * 16 + 2 * r2]     = a0[m];
            pb[w * 264 + (bq + 4 * m) * 16 + 2 * r2 + 1] = a1[m];
        }
    }
    __syncthreads();
    {
        float g = bias1;
        #pragma unroll
        for (int ww = 0; ww < 8; ++ww) g += pb[ww * 264 + tid];
        gb[(tid >> 4) * 17 + (tid & 15)] = g;
    }
    __syncthreads();
    if (tid < 64) {
        float gi = gb[cb * 17 + 0  + cu];
        float gf = gb[cb * 17 + 4  + cu];
        float gg = gb[cb * 17 + 8  + cu];
        float go = gb[cb * 17 + 12 + cu];
        float iv = expf(gi);
        float fv = 1.f / (1.f + expf(-gf));
        float gv = tanhf(gg);
        float ov = 1.f / (1.f + expf(-go));
        float nv = fmaf(fv, n1s[tid], iv);
        float cv = fmaf(fv, c1s[tid], iv * gv);
        float hv = ov * (cv / (nv + 1e-8f));
        out[(size_t)(TT - 1) * BH + hidx] = hv;

        // Final states after output_seq: hn[2,B,H], cn[2,B,H], nn[2,B,H]
        size_t base = (size_t)TT * BH;
        out[base + 0 * BH + hidx] = hf0[tid];
        out[base + 1 * BH + hidx] = hv;
        out[base + 2 * BH + hidx] = c0s[tid];
        out[base + 3 * BH + hidx] = cv;
        out[base + 4 * BH + hidx] = n0s[tid];
        out[base + 5 * BH + hidx] = nv;
    }
}

extern "C" void kernel_launch(void* const* d_in, const int* in_sizes, int n_in,
                              void* d_out, int out_size) {
    (void)in_sizes; (void)n_in; (void)out_size;
    const float* input  = (const float*)d_in[0];
    const float* w_ih0  = (const float*)d_in[1];
    const float* w_hh0  = (const float*)d_in[2];
    const float* b0     = (const float*)d_in[3];
    const float* w_ih1  = (const float*)d_in[4];
    const float* w_hh1  = (const float*)d_in[5];
    const float* b1     = (const float*)d_in[6];
    float* out = (float*)d_out;

    int smem_bytes = (3 * ROWS * 512 + 2 * BATCH * 516 + 8 * 264 + BATCH * 17
                      + 6 * 64 + 16) * 4;
    cudaFuncSetAttribute(slstm_kernel, cudaFuncAttributeMaxDynamicSharedMemorySize, smem_bytes);

    init_kernel<<<1, 64>>>();
    x0_gemm_kernel<<<dim3(G4 / 64, (TT * BATCH) / 64), 256>>>(input, w_ih0, b0);
    slstm_kernel<<<NCTA, NTH, smem_bytes>>>(w_hh0, w_ih1, w_hh1, b1, out);
}

// round 4
// speedup vs baseline: 1.7080x; 1.0417x over previous
#include <cuda_runtime.h>
#include <math.h>

#define TT    2048
#define BATCH 16
#define HD    512
#define G4    2048
#define NCTA  128
#define NTH   256
#define ROWS  16
#define HU    4
#define BH    (BATCH * HD)

typedef unsigned long long u64;

__device__ __forceinline__ u64 fma2(u64 a, u64 b, u64 c) {
    u64 d;
    asm("fma.rn.f32x2 %0, %1, %2, %3;" : "=l"(d) : "l"(a), "l"(b), "l"(c));
    return d;
}
__device__ __forceinline__ u64 pk2(float a, float b) {
    u64 d;
    asm("mov.b64 %0, {%1, %2};" : "=l"(d) : "f"(a), "f"(b));
    return d;
}
__device__ __forceinline__ float lo_f(u64 v) { return __uint_as_float((unsigned)v); }
__device__ __forceinline__ float hi_f(u64 v) { return __uint_as_float((unsigned)(v >> 32)); }

// Scratch (__device__ globals per allocation-free rules)
__device__ float g_x0[(size_t)TT * NCTA * 256];   // [t][cta][b][16 local rows]
__device__ float g_h0[2][BH];
__device__ float g_h1[2][BH];
__device__ unsigned g_ctr[64];                    // [0]=A (h0 steps), [32]=B (h1 steps)

__device__ __forceinline__ void cta_arrive(unsigned* p) {
    asm volatile("red.release.gpu.add.u32 [%0], %1;" :: "l"(p), "r"(1u) : "memory");
}
__device__ __forceinline__ void cta_spin(unsigned* p, unsigned tgt) {
    unsigned v;
    do {
        asm volatile("ld.acquire.gpu.u32 %0, [%1];" : "=r"(v) : "l"(p) : "memory");
    } while (v < tgt);
}

__global__ void init_kernel() {
    int i = blockIdx.x * blockDim.x + threadIdx.x;
    if (i < 64) g_ctr[i] = 0u;
}

// ---------------------------------------------------------------------------
// X0 GEMM with packed-j f32x2 FMAs.
// ---------------------------------------------------------------------------
__global__ void __launch_bounds__(256) x0_gemm_kernel(
    const float* __restrict__ A, const float* __restrict__ W,
    const float* __restrict__ bias)
{
    __shared__ float As[16][68];
    __shared__ float Ws[16][68];
    int tid = threadIdx.x;
    int tx = tid & 15, ty = tid >> 4;
    int m0 = blockIdx.y * 64, n0 = blockIdx.x * 64;
    int lr = tid >> 2;
    int lc = (tid & 3) << 2;
    u64 acc2[4][2] = {};
    for (int k0 = 0; k0 < 512; k0 += 16) {
        float4 av = *(const float4*)&A[(size_t)(m0 + lr) * 512 + k0 + lc];
        float4 wv = *(const float4*)&W[(size_t)(n0 + lr) * 512 + k0 + lc];
        As[lc + 0][lr] = av.x; As[lc + 1][lr] = av.y;
        As[lc + 2][lr] = av.z; As[lc + 3][lr] = av.w;
        Ws[lc + 0][lr] = wv.x; Ws[lc + 1][lr] = wv.y;
        Ws[lc + 2][lr] = wv.z; Ws[lc + 3][lr] = wv.w;
        __syncthreads();
        #pragma unroll
        for (int k = 0; k < 16; ++k) {
            float4 a4 = *(const float4*)&As[k][ty * 4];
            ulonglong2 w2 = *(const ulonglong2*)&Ws[k][tx * 4];
            u64 pa0 = pk2(a4.x, a4.x);
            u64 pa1 = pk2(a4.y, a4.y);
            u64 pa2 = pk2(a4.z, a4.z);
            u64 pa3 = pk2(a4.w, a4.w);
            acc2[0][0] = fma2(pa0, w2.x, acc2[0][0]);
            acc2[0][1] = fma2(pa0, w2.y, acc2[0][1]);
            acc2[1][0] = fma2(pa1, w2.x, acc2[1][0]);
            acc2[1][1] = fma2(pa1, w2.y, acc2[1][1]);
            acc2[2][0] = fma2(pa2, w2.x, acc2[2][0]);
            acc2[2][1] = fma2(pa2, w2.y, acc2[2][1]);
            acc2[3][0] = fma2(pa3, w2.x, acc2[3][0]);
            acc2[3][1] = fma2(pa3, w2.y, acc2[3][1]);
        }
        __syncthreads();
    }
    float4 bv = *(const float4*)&bias[n0 + tx * 4];
    int n = n0 + tx * 4;
    int g = n >> 9;
    int cta = (n >> 2) & 127;
    #pragma unroll
    for (int i = 0; i < 4; ++i) {
        int m = m0 + ty * 4 + i;
        int t = m >> 4, b = m & 15;
        float4 r;
        r.x = lo_f(acc2[i][0]) + bv.x; r.y = hi_f(acc2[i][0]) + bv.y;
        r.z = lo_f(acc2[i][1]) + bv.z; r.w = hi_f(acc2[i][1]) + bv.w;
        size_t dst = (((size_t)t * NCTA + cta) * 16 + b) * 16 + g * 4;
        *(float4*)&g_x0[dst] = r;
    }
}

// ---------------------------------------------------------------------------
// Persistent recurrent kernel, layer-pipelined, packed f32x2 GEMMs.
// ---------------------------------------------------------------------------
__global__ void __launch_bounds__(NTH, 1) slstm_kernel(
    const float* __restrict__ w_hh0,
    const float* __restrict__ w_ih1,
    const float* __restrict__ w_hh1,
    const float* __restrict__ b1,
    float* __restrict__ out)
{
    extern __shared__ float sm[];
    float* w0s  = sm;                        // 2048 f4 (perm layout)
    float* w1is = w0s  + ROWS * 512;
    float* w1hs = w1is + ROWS * 512;
    float* h0b  = w1hs + ROWS * 512;         // 16 x 129 f4
    float* h1b  = h0b  + BATCH * 516;
    float* pb   = h1b  + BATCH * 516;        // 8 warps x 264
    float* gb   = pb   + 8 * 264;            // 16 x 17
    float* c0s  = gb   + BATCH * 17;
    float* n0s  = c0s + 64;
    float* c1s  = n0s + 64;
    float* n1s  = c1s + 64;
    float* hf0  = n1s + 64;
    float* hf1  = hf0 + 64;
    float* b1s  = hf1 + 64;                  // 16

    const int cta  = blockIdx.x;
    const int tid  = threadIdx.x;
    const int w    = tid >> 5;
    const int lane = tid & 31;
    const int r2   = lane >> 2;
    const int bq   = lane & 3;

    float4* w0f  = (float4*)w0s;
    float4* w1if = (float4*)w1is;
    float4* w1hf = (float4*)w1hs;
    float4* h0f  = (float4*)h0b;
    float4* h1f  = (float4*)h1b;
    const ulonglong2* W0  = (const ulonglong2*)w0s;
    const ulonglong2* W1I = (const ulonglong2*)w1is;
    const ulonglong2* W1H = (const ulonglong2*)w1hs;
    const ulonglong2* H0  = (const ulonglong2*)h0b;
    const ulonglong2* H1  = (const ulonglong2*)h1b;

    // Load weight slices into smem, permuted: f4 (row,c) -> c*16 + (row&1)*8 + (row>>1)
    #pragma unroll
    for (int i = 0; i < 8; ++i) {
        int idx = tid + i * NTH;
        int r = idx >> 7;
        int c = idx & 127;
        int grow = (r >> 2) * HD + cta * HU + (r & 3);
        int dst = c * 16 + (r & 1) * 8 + (r >> 1);
        w0f[dst]  = ((const float4*)(w_hh0 + (size_t)grow * 512))[c];
        w1if[dst] = ((const float4*)(w_ih1 + (size_t)grow * 512))[c];
        w1hf[dst] = ((const float4*)(w_hh1 + (size_t)grow * 512))[c];
    }
    if (tid < ROWS) {
        int grow = (tid >> 2) * HD + cta * HU + (tid & 3);
        b1s[tid] = b1[grow];
    }
    for (int i = tid; i < BATCH * 516; i += NTH) { h0b[i] = 0.f; h1b[i] = 0.f; }
    if (tid < 64) { c0s[tid] = 0.f; n0s[tid] = 0.f; c1s[tid] = 0.f; n1s[tid] = 0.f; }
    __syncthreads();

    const int kb = w * 16;
    const int cb = tid >> 2, cu = tid & 3;
    const int hidx = cb * HD + cta * HU + cu;
    const float bias1 = b1s[tid & 15];
    unsigned* ctrA = &g_ctr[0];
    unsigned* ctrB = &g_ctr[32];

    for (int t = 0; t < TT; ++t) {
        float x0v = __ldcg(&g_x0[(((size_t)t * NCTA + cta) * 256) + tid]);

        // ---- L0 GEMM (h0f = h0(t-1)), packed pairs along k ----
        u64 p0[4] = {0ull, 0ull, 0ull, 0ull};
        u64 p1[4] = {0ull, 0ull, 0ull, 0ull};
        #pragma unroll
        for (int kv = 0; kv < 16; ++kv) {
            int k4 = kb + kv;
            ulonglong2 wa = W0[k4 * 16 + r2];
            ulonglong2 wb = W0[k4 * 16 + 8 + r2];
            #pragma unroll
            for (int m = 0; m < 4; ++m) {
                ulonglong2 h = H0[(bq + 4 * m) * 129 + k4];
                p0[m] = fma2(wa.x, h.x, p0[m]);
                p0[m] = fma2(wa.y, h.y, p0[m]);
                p1[m] = fma2(wb.x, h.x, p1[m]);
                p1[m] = fma2(wb.y, h.y, p1[m]);
            }
        }
        #pragma unroll
        for (int m = 0; m < 4; ++m) {
            pb[w * 264 + (bq + 4 * m) * 16 + 2 * r2]     = lo_f(p0[m]) + hi_f(p0[m]);
            pb[w * 264 + (bq + 4 * m) * 16 + 2 * r2 + 1] = lo_f(p1[m]) + hi_f(p1[m]);
        }
        __syncthreads();

        // ---- reduce0 (+x0) ; overlapped spin on B (h1(t-2) published) ----
        {
            float g = x0v;
            #pragma unroll
            for (int ww = 0; ww < 8; ++ww) g += pb[ww * 264 + tid];
            gb[(tid >> 4) * 17 + (tid & 15)] = g;
        }
        if (t >= 2 && tid == 255) cta_spin(ctrB, 128u * (unsigned)(t - 1));
        __syncthreads();

        // ---- cell0 + arrive A (warps 0-1) overlapped with h1 reload ----
        if (tid < 64) {
            float gi = gb[cb * 17 + 0  + cu];
            float gf = gb[cb * 17 + 4  + cu];
            float gg = gb[cb * 17 + 8  + cu];
            float go = gb[cb * 17 + 12 + cu];
            float iv = expf(gi);
            float fv = 1.f / (1.f + expf(-gf));
            float gv = tanhf(gg);
            float ov = 1.f / (1.f + expf(-go));
            float nv = fmaf(fv, n0s[tid], iv);
            float cv = fmaf(fv, c0s[tid], iv * gv);
            float hv = ov * (cv / (nv + 1e-8f));
            n0s[tid] = nv; c0s[tid] = cv; hf0[tid] = hv;
            g_h0[t & 1][hidx] = hv;
            asm volatile("bar.sync 1, 64;" ::: "memory");
            if (tid == 0) cta_arrive(ctrA);
        }
        if (t >= 2) {  // h1(t-2) lives in g_h1[t&1]
            const float4* s1 = (const float4*)g_h1[t & 1];
            #pragma unroll
            for (int i = 0; i < 8; ++i) {
                int idx = tid + i * NTH;
                int b = idx >> 7, c = idx & 127;
                h1f[b * 129 + c] = __ldcg(s1 + idx);
            }
        }
        __syncthreads();

        // ---- L1 GEMM for step t-1 (h0f = h0(t-1), h1f = h1(t-2)) ----
        if (t > 0) {
            u64 q0[4] = {0ull, 0ull, 0ull, 0ull};
            u64 q1[4] = {0ull, 0ull, 0ull, 0ull};
            #pragma unroll
            for (int kv = 0; kv < 16; ++kv) {
                int k4 = kb + kv;
                ulonglong2 wia = W1I[k4 * 16 + r2];
                ulonglong2 wib = W1I[k4 * 16 + 8 + r2];
                ulonglong2 wha = W1H[k4 * 16 + r2];
                ulonglong2 whb = W1H[k4 * 16 + 8 + r2];
                #pragma unroll
                for (int m = 0; m < 4; ++m) {
                    ulonglong2 x = H0[(bq + 4 * m) * 129 + k4];
                    ulonglong2 h = H1[(bq + 4 * m) * 129 + k4];
                    q0[m] = fma2(wia.x, x.x, q0[m]);
                    q0[m] = fma2(wia.y, x.y, q0[m]);
                    q0[m] = fma2(wha.x, h.x, q0[m]);
                    q0[m] = fma2(wha.y, h.y, q0[m]);
                    q1[m] = fma2(wib.x, x.x, q1[m]);
                    q1[m] = fma2(wib.y, x.y, q1[m]);
                    q1[m] = fma2(whb.x, h.x, q1[m]);
                    q1[m] = fma2(whb.y, h.y, q1[m]);
                }
            }
            #pragma unroll
            for (int m = 0; m < 4; ++m) {
                pb[w * 264 + (bq + 4 * m) * 16 + 2 * r2]     = lo_f(q0[m]) + hi_f(q0[m]);
                pb[w * 264 + (bq + 4 * m) * 16 + 2 * r2 + 1] = lo_f(q1[m]) + hi_f(q1[m]);
            }
            __syncthreads();
            {
                float g = bias1;
                #pragma unroll
                for (int ww = 0; ww < 8; ++ww) g += pb[ww * 264 + tid];
                gb[(tid >> 4) * 17 + (tid & 15)] = g;
            }
        }
        // spin on A (h0(t) published by all)
        if (tid == 255) cta_spin(ctrA, 128u * (unsigned)(t + 1));
        __syncthreads();

        // ---- cell1 (h1(t-1)) + arrive B, overlapped with h0 reload ----
        if (t > 0 && tid < 64) {
            float gi = gb[cb * 17 + 0  + cu];
            float gf = gb[cb * 17 + 4  + cu];
            float gg = gb[cb * 17 + 8  + cu];
            float go = gb[cb * 17 + 12 + cu];
            float iv = expf(gi);
            float fv = 1.f / (1.f + expf(-gf));
            float gv = tanhf(gg);
            float ov = 1.f / (1.f + expf(-go));
            float nv = fmaf(fv, n1s[tid], iv);
            float cv = fmaf(fv, c1s[tid], iv * gv);
            float hv = ov * (cv / (nv + 1e-8f));
            n1s[tid] = nv; c1s[tid] = cv; hf1[tid] = hv;
            g_h1[(t - 1) & 1][hidx] = hv;
            out[(size_t)(t - 1) * BH + hidx] = hv;
            asm volatile("bar.sync 1, 64;" ::: "memory");
            if (tid == 0) cta_arrive(ctrB);
        }
        {   // reload h0(t)
            const float4* s0 = (const float4*)g_h0[t & 1];
            #pragma unroll
            for (int i = 0; i < 8; ++i) {
                int idx = tid + i * NTH;
                int b = idx >> 7, c = idx & 127;
                h0f[b * 129 + c] = __ldcg(s0 + idx);
            }
        }
        __syncthreads();
    }

    // ---- epilogue: L1 step TT-1 ----
    if (tid == 255) cta_spin(ctrB, 128u * (unsigned)(TT - 1));
    __syncthreads();
    {
        const float4* s1 = (const float4*)g_h1[TT & 1];   // h1(TT-2)
        #pragma unroll
        for (int i = 0; i < 8; ++i) {
            int idx = tid + i * NTH;
            int b = idx >> 7, c = idx & 127;
            h1f[b * 129 + c] = __ldcg(s1 + idx);
        }
    }
    __syncthreads();
    {
        u64 q0[4] = {0ull, 0ull, 0ull, 0ull};
        u64 q1[4] = {0ull, 0ull, 0ull, 0ull};
        #pragma unroll
        for (int kv = 0; kv < 16; ++kv) {
            int k4 = kb + kv;
            ulonglong2 wia = W1I[k4 * 16 + r2];
            ulonglong2 wib = W1I[k4 * 16 + 8 + r2];
            ulonglong2 wha = W1H[k4 * 16 + r2];
            ulonglong2 whb = W1H[k4 * 16 + 8 + r2];
            #pragma unroll
            for (int m = 0; m < 4; ++m) {
                ulonglong2 x = H0[(bq + 4 * m) * 129 + k4];
                ulonglong2 h = H1[(bq + 4 * m) * 129 + k4];
                q0[m] = fma2(wia.x, x.x, q0[m]);
                q0[m] = fma2(wia.y, x.y, q0[m]);
                q0[m] = fma2(wha.x, h.x, q0[m]);
                q0[m] = fma2(wha.y, h.y, q0[m]);
                q1[m] = fma2(wib.x, x.x, q1[m]);
                q1[m] = fma2(wib.y, x.y, q1[m]);
                q1[m] = fma2(whb.x, h.x, q1[m]);
                q1[m] = fma2(whb.y, h.y, q1[m]);
            }
        }
        #pragma unroll
        for (int m = 0; m < 4; ++m) {
            pb[w * 264 + (bq + 4 * m) * 16 + 2 * r2]     = lo_f(q0[m]) + hi_f(q0[m]);
            pb[w * 264 + (bq + 4 * m) * 16 + 2 * r2 + 1] = lo_f(q1[m]) + hi_f(q1[m]);
        }
    }
    __syncthreads();
    {
        float g = bias1;
        #pragma unroll
        for (int ww = 0; ww < 8; ++ww) g += pb[ww * 264 + tid];
        gb[(tid >> 4) * 17 + (tid & 15)] = g;
    }
    __syncthreads();
    if (tid < 64) {
        float gi = gb[cb * 17 + 0  + cu];
        float gf = gb[cb * 17 + 4  + cu];
        float gg = gb[cb * 17 + 8  + cu];
        float go = gb[cb * 17 + 12 + cu];
        float iv = expf(gi);
        float fv = 1.f / (1.f + expf(-gf));
        float gv = tanhf(gg);
        float ov = 1.f / (1.f + expf(-go));
        float nv = fmaf(fv, n1s[tid], iv);
        float cv = fmaf(fv, c1s[tid], iv * gv);
        float hv = ov * (cv / (nv + 1e-8f));
        out[(size_t)(TT - 1) * BH + hidx] = hv;

        size_t base = (size_t)TT * BH;
        out[base + 0 * BH + hidx] = hf0[tid];
        out[base + 1 * BH + hidx] = hv;
        out[base + 2 * BH + hidx] = c0s[tid];
        out[base + 3 * BH + hidx] = cv;
        out[base + 4 * BH + hidx] = n0s[tid];
        out[base + 5 * BH + hidx] = nv;
    }
}

extern "C" void kernel_launch(void* const* d_in, const int* in_sizes, int n_in,
                              void* d_out, int out_size) {
    (void)in_sizes; (void)n_in; (void)out_size;
    const float* input  = (const float*)d_in[0];
    const float* w_ih0  = (const float*)d_in[1];
    const float* w_hh0  = (const float*)d_in[2];
    const float* b0     = (const float*)d_in[3];
    const float* w_ih1  = (const float*)d_in[4];
    const float* w_hh1  = (const float*)d_in[5];
    const float* b1     = (const float*)d_in[6];
    float* out = (float*)d_out;

    int smem_bytes = (3 * ROWS * 512 + 2 * BATCH * 516 + 8 * 264 + BATCH * 17
                      + 6 * 64 + 16) * 4;
    cudaFuncSetAttribute(slstm_kernel, cudaFuncAttributeMaxDynamicSharedMemorySize, smem_bytes);

    init_kernel<<<1, 64>>>();
    x0_gemm_kernel<<<dim3(G4 / 64, (TT * BATCH) / 64), 256>>>(input, w_ih0, b0);
    slstm_kernel<<<NCTA, NTH, smem_bytes>>>(w_hh0, w_ih1, w_hh1, b1, out);
}